// round 2
// baseline (speedup 1.0000x reference)
#include <cuda_runtime.h>
#include <math.h>

#define BDIM   2
#define SDIM   2048
#define NSTATE 1024
#define NHEAD  16
#define HDIM   64
#define MROWS  (BDIM*SDIM)            // 4096

__device__ __constant__ float kNegBig = -1e9f;
constexpr float SCALE_QK = 0.35355339059327373f;  // 64^-0.25

// Scratch (no allocations allowed — static device globals)
__device__ float g_Q [BDIM*NHEAD*SDIM*HDIM];   // [b][h][s][d], pre-scaled
__device__ float g_K [BDIM*NHEAD*SDIM*HDIM];   // [b][h][s][d], pre-scaled
__device__ float g_V [BDIM*NHEAD*SDIM*HDIM];   // [b][h][s][d]
__device__ float g_WV[MROWS*NSTATE];           // [b][s][h*d] row-major

// ---------------------------------------------------------------------------
// Classic 128x128x16 fp32 SGEMM, 256 threads, 8x8 micro-tiles.
// outSel: 0->g_Q, 1->g_K, 2->g_V (head layout), 3->Cext row-major
// inSel:  0->Ain, 1->g_WV
// epilogue: v = (acc + bias[n]) * scl
// ---------------------------------------------------------------------------
__global__ __launch_bounds__(256, 2)
void gemm128(const float* __restrict__ Ain, const float* __restrict__ Bmat,
             const float* __restrict__ bias, float* __restrict__ Cext,
             int M, int N, int K, float scl, int inSel, int outSel)
{
    const float* A = inSel ? g_WV : Ain;
    __shared__ float As[16][132];
    __shared__ float Bs[16][132];

    int tid = threadIdx.x;
    int m0 = blockIdx.y * 128, n0 = blockIdx.x * 128;
    int tx = tid & 15, ty = tid >> 4;

    float acc[8][8];
#pragma unroll
    for (int i = 0; i < 8; i++)
#pragma unroll
        for (int j = 0; j < 8; j++) acc[i][j] = 0.f;

    for (int k0 = 0; k0 < K; k0 += 16) {
#pragma unroll
        for (int i = 0; i < 2; i++) {
            int f = tid + i * 256;
            int ar = f >> 2, ac = (f & 3) << 2;
            float4 av = *(const float4*)(A + (size_t)(m0 + ar) * K + k0 + ac);
            As[ac][ar] = av.x; As[ac + 1][ar] = av.y;
            As[ac + 2][ar] = av.z; As[ac + 3][ar] = av.w;
            int br = f >> 5, bc = (f & 31) << 2;
            *(float4*)&Bs[br][bc] =
                *(const float4*)(Bmat + (size_t)(k0 + br) * N + n0 + bc);
        }
        __syncthreads();
#pragma unroll
        for (int kk = 0; kk < 16; kk++) {
            float a[8], bb[8];
            *(float4*)(a)      = *(float4*)&As[kk][ty * 8];
            *(float4*)(a + 4)  = *(float4*)&As[kk][ty * 8 + 4];
            *(float4*)(bb)     = *(float4*)&Bs[kk][tx * 8];
            *(float4*)(bb + 4) = *(float4*)&Bs[kk][tx * 8 + 4];
#pragma unroll
            for (int i = 0; i < 8; i++)
#pragma unroll
                for (int j = 0; j < 8; j++) acc[i][j] += a[i] * bb[j];
        }
        __syncthreads();
    }

#pragma unroll
    for (int i = 0; i < 8; i++) {
        int m = m0 + ty * 8 + i;
#pragma unroll
        for (int j = 0; j < 8; j++) {
            int n = n0 + tx * 8 + j;
            float v = acc[i][j];
            if (bias) v += bias[n];
            v *= scl;
            if (outSel == 3) {
                Cext[(size_t)m * N + n] = v;
            } else {
                float* dst = (outSel == 0) ? g_Q : ((outSel == 1) ? g_K : g_V);
                int b = m >> 11, s = m & (SDIM - 1);
                int h = n >> 6,  d = n & (HDIM - 1);
                dst[((size_t)(b * NHEAD + h) * SDIM + s) * HDIM + d] = v;
            }
        }
    }
}

// ---------------------------------------------------------------------------
// Fill strictly-upper (k > q) region of qk with -1e9 (exact per reference).
// ---------------------------------------------------------------------------
__global__ void fill_mask(float* __restrict__ qk)
{
    size_t i4 = (size_t)blockIdx.x * 256 + threadIdx.x;   // over 2^25 float4s
    size_t base = i4 * 4;
    int k = (int)(base & (SDIM - 1));
    size_t row = base >> 11;
    int q = (int)(row & (SDIM - 1));
    if (k > q) {
        float4 v = make_float4(-1e9f, -1e9f, -1e9f, -1e9f);
        *(float4*)(qk + base) = v;
    } else if (k + 3 > q) {
#pragma unroll
        for (int e = 0; e < 4; e++)
            if (k + e > q) qk[base + e] = -1e9f;
    }
}

// ---------------------------------------------------------------------------
// Flash attention (causal) that ALSO writes qk logits to gmem.
// CTA: 32 q-rows, k-tiles of 64. 256 threads: r=tid>>3 (row), l=tid&7 (lane).
// Each thread handles k columns {l, l+8, ..., l+56} of the tile (bank-safe),
// and keeps a partial O accumulator over all 64 d.
// ---------------------------------------------------------------------------
__global__ __launch_bounds__(256, 2)
void flash_kernel(float* __restrict__ qk_out)
{
    int qb = blockIdx.x, h = blockIdx.y, b = blockIdx.z;
    int bh = b * NHEAD + h;
    int q0 = qb * 32;

    __shared__ float Qs[32][68];
    __shared__ float Ks[64][68];
    __shared__ float Vs[64][68];

    int tid = threadIdx.x;
    int r = tid >> 3, l = tid & 7;
    int q = q0 + r;

    const float* Qg = g_Q + (size_t)bh * SDIM * HDIM;
    const float* Kg = g_K + (size_t)bh * SDIM * HDIM;
    const float* Vg = g_V + (size_t)bh * SDIM * HDIM;

    // load Q block [32][64]
#pragma unroll
    for (int i = 0; i < 2; i++) {
        int f = tid + i * 256;
        int row = f >> 4, c = (f & 15) << 2;
        *(float4*)&Qs[row][c] = *(const float4*)(Qg + (size_t)(q0 + row) * HDIM + c);
    }

    float oacc[64];
#pragma unroll
    for (int d = 0; d < 64; d++) oacc[d] = 0.f;
    float mrow = -INFINITY, lrow = 0.f;

    int nTiles = (q0 + 32 + 63) >> 6;
    for (int t = 0; t < nTiles; t++) {
        int k0 = t * 64;
        __syncthreads();
#pragma unroll
        for (int i = 0; i < 4; i++) {
            int f = tid + i * 256;
            int row = f >> 4, c = (f & 15) << 2;
            *(float4*)&Ks[row][c] = *(const float4*)(Kg + (size_t)(k0 + row) * HDIM + c);
            *(float4*)&Vs[row][c] = *(const float4*)(Vg + (size_t)(k0 + row) * HDIM + c);
        }
        __syncthreads();

        // S = Qs[r] . Ks[kk]  for kk = j*8 + l
        float sv[8];
#pragma unroll
        for (int j = 0; j < 8; j++) sv[j] = 0.f;
#pragma unroll
        for (int d = 0; d < 64; d += 4) {
            float4 qv = *(float4*)&Qs[r][d];
#pragma unroll
            for (int j = 0; j < 8; j++) {
                float4 kv = *(float4*)&Ks[j * 8 + l][d];
                sv[j] += qv.x * kv.x + qv.y * kv.y + qv.z * kv.z + qv.w * kv.w;
            }
        }

        // causal mask + dump logits
        float tmax = -INFINITY;
        float* qkrow = qk_out + ((size_t)bh * SDIM + q) * SDIM + k0;
#pragma unroll
        for (int j = 0; j < 8; j++) {
            int kg = k0 + j * 8 + l;
            if (kg > q) sv[j] = -1e9f;
            tmax = fmaxf(tmax, sv[j]);
            qkrow[j * 8 + l] = sv[j];
        }

        // row max over the 8 lanes of this row group
        tmax = fmaxf(tmax, __shfl_xor_sync(0xffffffffu, tmax, 1));
        tmax = fmaxf(tmax, __shfl_xor_sync(0xffffffffu, tmax, 2));
        tmax = fmaxf(tmax, __shfl_xor_sync(0xffffffffu, tmax, 4));
        float mnew = fmaxf(mrow, tmax);
        float fac = __expf(mrow - mnew);

        float p[8], psum = 0.f;
#pragma unroll
        for (int j = 0; j < 8; j++) { p[j] = __expf(sv[j] - mnew); psum += p[j]; }
        psum += __shfl_xor_sync(0xffffffffu, psum, 1);
        psum += __shfl_xor_sync(0xffffffffu, psum, 2);
        psum += __shfl_xor_sync(0xffffffffu, psum, 4);
        lrow = lrow * fac + psum;
        mrow = mnew;

#pragma unroll
        for (int d = 0; d < 64; d++) oacc[d] *= fac;
#pragma unroll
        for (int j = 0; j < 8; j++) {
            float pj = p[j];
#pragma unroll
            for (int d = 0; d < 64; d += 4) {
                float4 vv = *(float4*)&Vs[j * 8 + l][d];
                oacc[d]     += pj * vv.x;
                oacc[d + 1] += pj * vv.y;
                oacc[d + 2] += pj * vv.z;
                oacc[d + 3] += pj * vv.w;
            }
        }
    }

    // Recursive-halving reduce across the 8 lanes; lane l ends owning d=l*8..l*8+7
#pragma unroll
    for (int d = 0; d < 32; d++) {
        float a = oacc[d], bb = oacc[d + 32];
        float send = (l & 4) ? a : bb;
        float recv = __shfl_xor_sync(0xffffffffu, send, 4);
        oacc[d] = ((l & 4) ? bb : a) + recv;
    }
#pragma unroll
    for (int d = 0; d < 16; d++) {
        float a = oacc[d], bb = oacc[d + 16];
        float send = (l & 2) ? a : bb;
        float recv = __shfl_xor_sync(0xffffffffu, send, 2);
        oacc[d] = ((l & 2) ? bb : a) + recv;
    }
#pragma unroll
    for (int d = 0; d < 8; d++) {
        float a = oacc[d], bb = oacc[d + 8];
        float send = (l & 1) ? a : bb;
        float recv = __shfl_xor_sync(0xffffffffu, send, 1);
        oacc[d] = ((l & 1) ? bb : a) + recv;
    }

    float inv = 1.f / lrow;
    float* wvrow = g_WV + ((size_t)(b * SDIM + q) * NHEAD + h) * HDIM + l * 8;
    float4 o0 = make_float4(oacc[0] * inv, oacc[1] * inv, oacc[2] * inv, oacc[3] * inv);
    float4 o1 = make_float4(oacc[4] * inv, oacc[5] * inv, oacc[6] * inv, oacc[7] * inv);
    *(float4*)(wvrow)     = o0;
    *(float4*)(wvrow + 4) = o1;
}

// ---------------------------------------------------------------------------
extern "C" void kernel_launch(void* const* d_in, const int* in_sizes, int n_in,
                              void* d_out, int out_size)
{
    const float* x  = (const float*)d_in[0];
    // d_in[1] = mask (implemented analytically)
    const float* Wq = (const float*)d_in[2];
    const float* bq = (const float*)d_in[3];
    const float* Wk = (const float*)d_in[4];
    const float* Wv = (const float*)d_in[5];
    const float* bv = (const float*)d_in[6];
    const float* Wo = (const float*)d_in[7];
    const float* bo = (const float*)d_in[8];

    float* out = (float*)d_out;                       // [b,s,1024]
    float* qk  = out + (size_t)BDIM * SDIM * NSTATE;  // [b,h,s,s]

    dim3 gProj(NSTATE / 128, MROWS / 128);            // (8, 32)
    gemm128<<<gProj, 256>>>(x, Wq, bq, nullptr, MROWS, NSTATE, NSTATE, SCALE_QK, 0, 0);
    gemm128<<<gProj, 256>>>(x, Wk, nullptr, nullptr, MROWS, NSTATE, NSTATE, SCALE_QK, 0, 1);
    gemm128<<<gProj, 256>>>(x, Wv, bv, nullptr, MROWS, NSTATE, NSTATE, 1.0f, 0, 2);

    size_t qk_f4 = (size_t)BDIM * NHEAD * SDIM * SDIM / 4;   // 2^25
    fill_mask<<<(unsigned)(qk_f4 / 256), 256>>>(qk);

    flash_kernel<<<dim3(SDIM / 32, NHEAD, BDIM), 256>>>(qk);

    gemm128<<<gProj, 256>>>(nullptr, Wo, bo, out, MROWS, NSTATE, NSTATE, 1.0f, 1, 3);
}

// round 4
// speedup vs baseline: 1.2735x; 1.2735x over previous
#include <cuda_runtime.h>
#include <cuda_bf16.h>
#include <math.h>
#include <cstdint>

#define BDIM   2
#define SDIM   2048
#define NSTATE 1024
#define NHEAD  16
#define HDIM   64
#define MROWS  (BDIM*SDIM)            // 4096

constexpr float SCALE_QK = 0.35355339059327373f;  // 64^-0.25

// ---------------- scratch (static device globals; no allocs allowed) --------
__device__ float g_Q [BDIM*NHEAD*SDIM*HDIM];   // [b][h][s][d], pre-scaled
__device__ float g_K [BDIM*NHEAD*SDIM*HDIM];
__device__ float g_V [BDIM*NHEAD*SDIM*HDIM];
__device__ float g_WV[MROWS*NSTATE];           // [b][s][h*d] row-major

__device__ __nv_bfloat16 g_xh [MROWS*NSTATE];
__device__ __nv_bfloat16 g_xl [MROWS*NSTATE];
__device__ __nv_bfloat16 g_WVh[MROWS*NSTATE];
__device__ __nv_bfloat16 g_WVl[MROWS*NSTATE];
__device__ __nv_bfloat16 g_Wth[4*NSTATE*NSTATE];  // transposed weights [n][k], order q,k,v,o
__device__ __nv_bfloat16 g_Wtl[4*NSTATE*NSTATE];

// ---------------- conversion helpers ---------------------------------------
__device__ __forceinline__ void split_bf16(float v, __nv_bfloat16& h, __nv_bfloat16& l) {
    h = __float2bfloat16_rn(v);
    l = __float2bfloat16_rn(v - __bfloat162float(h));
}

__global__ void convert_x_kernel(const float* __restrict__ x) {
    size_t i = (size_t)blockIdx.x * 256 + threadIdx.x;
    float4 v = ((const float4*)x)[i];
    __nv_bfloat16 h[4], l[4];
    split_bf16(v.x, h[0], l[0]); split_bf16(v.y, h[1], l[1]);
    split_bf16(v.z, h[2], l[2]); split_bf16(v.w, h[3], l[3]);
    ((uint2*)g_xh)[i] = *(uint2*)h;
    ((uint2*)g_xl)[i] = *(uint2*)l;
}
__global__ void convert_wv_kernel() {
    size_t i = (size_t)blockIdx.x * 256 + threadIdx.x;
    float4 v = ((const float4*)g_WV)[i];
    __nv_bfloat16 h[4], l[4];
    split_bf16(v.x, h[0], l[0]); split_bf16(v.y, h[1], l[1]);
    split_bf16(v.z, h[2], l[2]); split_bf16(v.w, h[3], l[3]);
    ((uint2*)g_WVh)[i] = *(uint2*)h;
    ((uint2*)g_WVl)[i] = *(uint2*)l;
}

// Transpose + split 4 weight matrices: Wt[n][k] = W[k][n]
__global__ void transpose_convert(const float* __restrict__ W0, const float* __restrict__ W1,
                                  const float* __restrict__ W2, const float* __restrict__ W3) {
    __shared__ float T[32][33];
    int w = blockIdx.z;
    const float* W = (w == 0) ? W0 : (w == 1) ? W1 : (w == 2) ? W2 : W3;
    int n0 = blockIdx.x * 32, k0 = blockIdx.y * 32;
    int tx = threadIdx.x, ty = threadIdx.y;
#pragma unroll
    for (int r = 0; r < 4; r++) {
        int kl = ty + 8 * r;
        T[kl][tx] = W[(size_t)(k0 + kl) * NSTATE + n0 + tx];
    }
    __syncthreads();
    size_t base = (size_t)w * NSTATE * NSTATE;
#pragma unroll
    for (int r = 0; r < 4; r++) {
        int nl = ty + 8 * r;
        float v = T[tx][nl];
        __nv_bfloat16 h, l;
        split_bf16(v, h, l);
        size_t o = base + (size_t)(n0 + nl) * NSTATE + k0 + tx;
        g_Wth[o] = h;
        g_Wtl[o] = l;
    }
}

// ---------------- warp-mma bf16 hi/lo GEMM ----------------------------------
// C(4096x1024) = A(4096x1024) @ W(1024x1024); B stored transposed [n][k].
// CTA tile 128x128, BK=32, 8 warps (2m x 4n), warp tile 64x32 via m16n8k16.
__device__ __forceinline__ void mma16816(float* c, const uint32_t* a, const uint32_t* b) {
    asm volatile(
        "mma.sync.aligned.m16n8k16.row.col.f32.bf16.bf16.f32 "
        "{%0,%1,%2,%3}, {%4,%5,%6,%7}, {%8,%9}, {%0,%1,%2,%3};"
        : "+f"(c[0]), "+f"(c[1]), "+f"(c[2]), "+f"(c[3])
        : "r"(a[0]), "r"(a[1]), "r"(a[2]), "r"(a[3]), "r"(b[0]), "r"(b[1]));
}

#define LDW 40   // padded row length (bf16) for 128x32 tiles

__device__ __forceinline__ void load_tile32(const __nv_bfloat16* __restrict__ src,
                                            int rowBase, int k0,
                                            __nv_bfloat16 (*S)[LDW], int tid) {
#pragma unroll
    for (int i = 0; i < 4; i++) {
        int idx = tid + i * 256;
        int row = idx >> 3, seg = idx & 7;
        uint2 v = *(const uint2*)(src + (size_t)(rowBase + row) * NSTATE + k0 + seg * 4);
        *(uint2*)&S[row][seg * 4] = v;
    }
}

__global__ __launch_bounds__(256)
void gemm_mma(const float* __restrict__ bias, float* __restrict__ Cext,
              float scl, int aSel, int wIdx, int outSel)
{
    __shared__ __nv_bfloat16 Ash[128][LDW], Asl[128][LDW];
    __shared__ __nv_bfloat16 Bsh[128][LDW], Bsl[128][LDW];

    int tid = threadIdx.x;
    int wid = tid >> 5, l = tid & 31;
    int wm = wid >> 2, wn = wid & 3;          // 2 x 4 warp grid
    int mw0 = wm * 64, nw0 = wn * 32;
    int m0 = blockIdx.y * 128, n0 = blockIdx.x * 128;
    int gr = l >> 2, kc = (l & 3) * 2;

    const __nv_bfloat16* A_h = aSel ? g_WVh : g_xh;
    const __nv_bfloat16* A_l = aSel ? g_WVl : g_xl;
    const __nv_bfloat16* B_h = g_Wth + (size_t)wIdx * NSTATE * NSTATE;
    const __nv_bfloat16* B_l = g_Wtl + (size_t)wIdx * NSTATE * NSTATE;

    float c[4][4][4];
#pragma unroll
    for (int mt = 0; mt < 4; mt++)
#pragma unroll
        for (int nt = 0; nt < 4; nt++)
#pragma unroll
            for (int e = 0; e < 4; e++) c[mt][nt][e] = 0.f;

    for (int k0 = 0; k0 < NSTATE; k0 += 32) {
        __syncthreads();
        load_tile32(A_h, m0, k0, Ash, tid);
        load_tile32(A_l, m0, k0, Asl, tid);
        load_tile32(B_h, n0, k0, Bsh, tid);
        load_tile32(B_l, n0, k0, Bsl, tid);
        __syncthreads();

#pragma unroll
        for (int kk = 0; kk < 32; kk += 16) {
            uint32_t bh[4][2], bl[4][2];
#pragma unroll
            for (int nt = 0; nt < 4; nt++) {
                int nr = nw0 + nt * 8 + gr;
                bh[nt][0] = *(uint32_t*)&Bsh[nr][kk + kc];
                bh[nt][1] = *(uint32_t*)&Bsh[nr][kk + kc + 8];
                bl[nt][0] = *(uint32_t*)&Bsl[nr][kk + kc];
                bl[nt][1] = *(uint32_t*)&Bsl[nr][kk + kc + 8];
            }
#pragma unroll
            for (int mt = 0; mt < 4; mt++) {
                int r = mw0 + mt * 16;
                uint32_t ah[4], al[4];
                ah[0] = *(uint32_t*)&Ash[r + gr][kk + kc];
                ah[1] = *(uint32_t*)&Ash[r + gr + 8][kk + kc];
                ah[2] = *(uint32_t*)&Ash[r + gr][kk + kc + 8];
                ah[3] = *(uint32_t*)&Ash[r + gr + 8][kk + kc + 8];
                al[0] = *(uint32_t*)&Asl[r + gr][kk + kc];
                al[1] = *(uint32_t*)&Asl[r + gr + 8][kk + kc];
                al[2] = *(uint32_t*)&Asl[r + gr][kk + kc + 8];
                al[3] = *(uint32_t*)&Asl[r + gr + 8][kk + kc + 8];
#pragma unroll
                for (int nt = 0; nt < 4; nt++) {
                    mma16816(c[mt][nt], ah, bh[nt]);
                    mma16816(c[mt][nt], ah, bl[nt]);
                    mma16816(c[mt][nt], al, bh[nt]);
                }
            }
        }
    }

    // epilogue: v = (acc + bias[n]) * scl
#pragma unroll
    for (int mt = 0; mt < 4; mt++) {
#pragma unroll
        for (int nt = 0; nt < 4; nt++) {
            int n = n0 + nw0 + nt * 8 + kc;          // cols n, n+1
            float b0 = bias ? bias[n] : 0.f;
            float b1 = bias ? bias[n + 1] : 0.f;
#pragma unroll
            for (int half = 0; half < 2; half++) {
                int m = m0 + mw0 + mt * 16 + gr + half * 8;
                float v0 = (c[mt][nt][half * 2 + 0] + b0) * scl;
                float v1 = (c[mt][nt][half * 2 + 1] + b1) * scl;
                if (outSel == 3) {
                    float2* p = (float2*)(Cext + (size_t)m * NSTATE + n);
                    *p = make_float2(v0, v1);
                } else {
                    float* dst = (outSel == 0) ? g_Q : ((outSel == 1) ? g_K : g_V);
                    int b = m >> 11, s = m & (SDIM - 1);
                    int h = n >> 6, d = n & (HDIM - 1);
                    float2* p = (float2*)(dst + ((size_t)(b * NHEAD + h) * SDIM + s) * HDIM + d);
                    *p = make_float2(v0, v1);
                }
            }
        }
    }
}

// ---------------- fill upper-triangle of qk with -1e9 ----------------------
__global__ void fill_mask(float* __restrict__ qk)
{
    size_t i4 = (size_t)blockIdx.x * 256 + threadIdx.x;
    size_t base = i4 * 4;
    int k = (int)(base & (SDIM - 1));
    size_t row = base >> 11;
    int q = (int)(row & (SDIM - 1));
    if (k > q) {
        float4 v = make_float4(-1e9f, -1e9f, -1e9f, -1e9f);
        *(float4*)(qk + base) = v;
    } else if (k + 3 > q) {
#pragma unroll
        for (int e = 0; e < 4; e++)
            if (k + e > q) qk[base + e] = -1e9f;
    }
}

// ---------------- fp32 SIMT flash attention (writes qk logits) -------------
__global__ __launch_bounds__(256, 2)
void flash_kernel(float* __restrict__ qk_out)
{
    int qb = blockIdx.x, h = blockIdx.y, b = blockIdx.z;
    int bh = b * NHEAD + h;
    int q0 = qb * 32;

    __shared__ float Qs[32][68];
    __shared__ float Ks[64][68];
    __shared__ float Vs[64][68];

    int tid = threadIdx.x;
    int r = tid >> 3, l = tid & 7;
    int q = q0 + r;

    const float* Qg = g_Q + (size_t)bh * SDIM * HDIM;
    const float* Kg = g_K + (size_t)bh * SDIM * HDIM;
    const float* Vg = g_V + (size_t)bh * SDIM * HDIM;

#pragma unroll
    for (int i = 0; i < 2; i++) {
        int f = tid + i * 256;
        int row = f >> 4, c = (f & 15) << 2;
        *(float4*)&Qs[row][c] = *(const float4*)(Qg + (size_t)(q0 + row) * HDIM + c);
    }

    float oacc[64];
#pragma unroll
    for (int d = 0; d < 64; d++) oacc[d] = 0.f;
    float mrow = -INFINITY, lrow = 0.f;

    int nTiles = (q0 + 32 + 63) >> 6;
    for (int t = 0; t < nTiles; t++) {
        int k0 = t * 64;
        __syncthreads();
#pragma unroll
        for (int i = 0; i < 4; i++) {
            int f = tid + i * 256;
            int row = f >> 4, c = (f & 15) << 2;
            *(float4*)&Ks[row][c] = *(const float4*)(Kg + (size_t)(k0 + row) * HDIM + c);
            *(float4*)&Vs[row][c] = *(const float4*)(Vg + (size_t)(k0 + row) * HDIM + c);
        }
        __syncthreads();

        float sv[8];
#pragma unroll
        for (int j = 0; j < 8; j++) sv[j] = 0.f;
#pragma unroll
        for (int d = 0; d < 64; d += 4) {
            float4 qv = *(float4*)&Qs[r][d];
#pragma unroll
            for (int j = 0; j < 8; j++) {
                float4 kv = *(float4*)&Ks[j * 8 + l][d];
                sv[j] += qv.x * kv.x + qv.y * kv.y + qv.z * kv.z + qv.w * kv.w;
            }
        }

        float tmax = -INFINITY;
        float* qkrow = qk_out + ((size_t)bh * SDIM + q) * SDIM + k0;
#pragma unroll
        for (int j = 0; j < 8; j++) {
            int kg = k0 + j * 8 + l;
            if (kg > q) sv[j] = -1e9f;
            tmax = fmaxf(tmax, sv[j]);
            qkrow[j * 8 + l] = sv[j];
        }

        tmax = fmaxf(tmax, __shfl_xor_sync(0xffffffffu, tmax, 1));
        tmax = fmaxf(tmax, __shfl_xor_sync(0xffffffffu, tmax, 2));
        tmax = fmaxf(tmax, __shfl_xor_sync(0xffffffffu, tmax, 4));
        float mnew = fmaxf(mrow, tmax);
        float fac = __expf(mrow - mnew);

        float p[8], psum = 0.f;
#pragma unroll
        for (int j = 0; j < 8; j++) { p[j] = __expf(sv[j] - mnew); psum += p[j]; }
        psum += __shfl_xor_sync(0xffffffffu, psum, 1);
        psum += __shfl_xor_sync(0xffffffffu, psum, 2);
        psum += __shfl_xor_sync(0xffffffffu, psum, 4);
        lrow = lrow * fac + psum;
        mrow = mnew;

#pragma unroll
        for (int d = 0; d < 64; d++) oacc[d] *= fac;
#pragma unroll
        for (int j = 0; j < 8; j++) {
            float pj = p[j];
#pragma unroll
            for (int d = 0; d < 64; d += 4) {
                float4 vv = *(float4*)&Vs[j * 8 + l][d];
                oacc[d]     += pj * vv.x;
                oacc[d + 1] += pj * vv.y;
                oacc[d + 2] += pj * vv.z;
                oacc[d + 3] += pj * vv.w;
            }
        }
    }

#pragma unroll
    for (int d = 0; d < 32; d++) {
        float a = oacc[d], bb = oacc[d + 32];
        float send = (l & 4) ? a : bb;
        float recv = __shfl_xor_sync(0xffffffffu, send, 4);
        oacc[d] = ((l & 4) ? bb : a) + recv;
    }
#pragma unroll
    for (int d = 0; d < 16; d++) {
        float a = oacc[d], bb = oacc[d + 16];
        float send = (l & 2) ? a : bb;
        float recv = __shfl_xor_sync(0xffffffffu, send, 2);
        oacc[d] = ((l & 2) ? bb : a) + recv;
    }
#pragma unroll
    for (int d = 0; d < 8; d++) {
        float a = oacc[d], bb = oacc[d + 8];
        float send = (l & 1) ? a : bb;
        float recv = __shfl_xor_sync(0xffffffffu, send, 1);
        oacc[d] = ((l & 1) ? bb : a) + recv;
    }

    float inv = 1.f / lrow;
    float* wvrow = g_WV + ((size_t)(b * SDIM + q) * NHEAD + h) * HDIM + l * 8;
    float4 o0 = make_float4(oacc[0] * inv, oacc[1] * inv, oacc[2] * inv, oacc[3] * inv);
    float4 o1 = make_float4(oacc[4] * inv, oacc[5] * inv, oacc[6] * inv, oacc[7] * inv);
    *(float4*)(wvrow)     = o0;
    *(float4*)(wvrow + 4) = o1;
}

// ---------------------------------------------------------------------------
extern "C" void kernel_launch(void* const* d_in, const int* in_sizes, int n_in,
                              void* d_out, int out_size)
{
    const float* x  = (const float*)d_in[0];
    const float* Wq = (const float*)d_in[2];
    const float* bq = (const float*)d_in[3];
    const float* Wk = (const float*)d_in[4];
    const float* Wv = (const float*)d_in[5];
    const float* bv = (const float*)d_in[6];
    const float* Wo = (const float*)d_in[7];
    const float* bo = (const float*)d_in[8];

    float* out = (float*)d_out;                       // [b,s,1024]
    float* qk  = out + (size_t)BDIM * SDIM * NSTATE;  // [b,h,s,s]

    convert_x_kernel<<<MROWS * NSTATE / 4 / 256, 256>>>(x);
    transpose_convert<<<dim3(32, 32, 4), dim3(32, 8)>>>(Wq, Wk, Wv, Wo);

    dim3 g(NSTATE / 128, MROWS / 128);   // (8, 32)
    gemm_mma<<<g, 256>>>(bq, nullptr, SCALE_QK, 0, 0, 0);
    gemm_mma<<<g, 256>>>(nullptr, nullptr, SCALE_QK, 0, 1, 1);
    gemm_mma<<<g, 256>>>(bv, nullptr, 1.0f, 0, 2, 2);

    size_t qk_f4 = (size_t)BDIM * NHEAD * SDIM * SDIM / 4;
    fill_mask<<<(unsigned)(qk_f4 / 256), 256>>>(qk);

    flash_kernel<<<dim3(SDIM / 32, NHEAD, BDIM), 256>>>(qk);

    convert_wv_kernel<<<MROWS * NSTATE / 4 / 256, 256>>>();
    gemm_mma<<<g, 256>>>(bo, out, 1.0f, 1, 3, 3);
}

// round 5
// speedup vs baseline: 1.2819x; 1.0066x over previous
#include <cuda_runtime.h>
#include <cuda_bf16.h>
#include <math.h>
#include <cstdint>

#define BDIM   2
#define SDIM   2048
#define NSTATE 1024
#define NHEAD  16
#define HDIM   64
#define MROWS  (BDIM*SDIM)            // 4096

constexpr float SCALE_QK = 0.35355339059327373f;  // 64^-0.25

// ---------------- scratch (static device globals; no allocs allowed) --------
__device__ float g_Q [BDIM*NHEAD*SDIM*HDIM];   // [b][h][s][d], pre-scaled
__device__ float g_K [BDIM*NHEAD*SDIM*HDIM];
__device__ float g_V [BDIM*NHEAD*SDIM*HDIM];
__device__ float g_WV[MROWS*NSTATE];           // [b][s][h*d] row-major

__device__ __nv_bfloat16 g_xh [MROWS*NSTATE];
__device__ __nv_bfloat16 g_xl [MROWS*NSTATE];
__device__ __nv_bfloat16 g_WVh[MROWS*NSTATE];
__device__ __nv_bfloat16 g_WVl[MROWS*NSTATE];
__device__ __nv_bfloat16 g_Wth[4*NSTATE*NSTATE];  // transposed weights [n][k], order q,k,v,o
__device__ __nv_bfloat16 g_Wtl[4*NSTATE*NSTATE];

// ---------------- conversion helpers ---------------------------------------
__device__ __forceinline__ void split_bf16(float v, __nv_bfloat16& h, __nv_bfloat16& l) {
    h = __float2bfloat16_rn(v);
    l = __float2bfloat16_rn(v - __bfloat162float(h));
}

__global__ void convert_x_kernel(const float* __restrict__ x) {
    size_t i = (size_t)blockIdx.x * 256 + threadIdx.x;
    float4 v = ((const float4*)x)[i];
    __nv_bfloat16 h[4], l[4];
    split_bf16(v.x, h[0], l[0]); split_bf16(v.y, h[1], l[1]);
    split_bf16(v.z, h[2], l[2]); split_bf16(v.w, h[3], l[3]);
    ((uint2*)g_xh)[i] = *(uint2*)h;
    ((uint2*)g_xl)[i] = *(uint2*)l;
}
__global__ void convert_wv_kernel() {
    size_t i = (size_t)blockIdx.x * 256 + threadIdx.x;
    float4 v = ((const float4*)g_WV)[i];
    __nv_bfloat16 h[4], l[4];
    split_bf16(v.x, h[0], l[0]); split_bf16(v.y, h[1], l[1]);
    split_bf16(v.z, h[2], l[2]); split_bf16(v.w, h[3], l[3]);
    ((uint2*)g_WVh)[i] = *(uint2*)h;
    ((uint2*)g_WVl)[i] = *(uint2*)l;
}

// Transpose + split 4 weight matrices: Wt[n][k] = W[k][n]
__global__ void transpose_convert(const float* __restrict__ W0, const float* __restrict__ W1,
                                  const float* __restrict__ W2, const float* __restrict__ W3) {
    __shared__ float T[32][33];
    int w = blockIdx.z;
    const float* W = (w == 0) ? W0 : (w == 1) ? W1 : (w == 2) ? W2 : W3;
    int n0 = blockIdx.x * 32, k0 = blockIdx.y * 32;
    int tx = threadIdx.x, ty = threadIdx.y;
#pragma unroll
    for (int r = 0; r < 4; r++) {
        int kl = ty + 8 * r;
        T[kl][tx] = W[(size_t)(k0 + kl) * NSTATE + n0 + tx];
    }
    __syncthreads();
    size_t base = (size_t)w * NSTATE * NSTATE;
#pragma unroll
    for (int r = 0; r < 4; r++) {
        int nl = ty + 8 * r;
        float v = T[tx][nl];
        __nv_bfloat16 h, l;
        split_bf16(v, h, l);
        size_t o = base + (size_t)(n0 + nl) * NSTATE + k0 + tx;
        g_Wth[o] = h;
        g_Wtl[o] = l;
    }
}

// ---------------- warp-mma bf16 hi/lo GEMM ----------------------------------
// C(4096x1024) = A(4096x1024) @ W(1024x1024); B stored transposed [n][k].
// CTA tile 128x128, BK=32, 8 warps (2m x 4n), warp tile 64x32 via m16n8k16.
__device__ __forceinline__ void mma16816(float* c, const uint32_t* a, const uint32_t* b) {
    asm volatile(
        "mma.sync.aligned.m16n8k16.row.col.f32.bf16.bf16.f32 "
        "{%0,%1,%2,%3}, {%4,%5,%6,%7}, {%8,%9}, {%0,%1,%2,%3};"
        : "+f"(c[0]), "+f"(c[1]), "+f"(c[2]), "+f"(c[3])
        : "r"(a[0]), "r"(a[1]), "r"(a[2]), "r"(a[3]), "r"(b[0]), "r"(b[1]));
}

#define LDW 40   // padded row length (bf16) for 128x32 tiles

__device__ __forceinline__ void load_tile32(const __nv_bfloat16* __restrict__ src,
                                            int rowBase, int k0,
                                            __nv_bfloat16 (*S)[LDW], int tid) {
#pragma unroll
    for (int i = 0; i < 4; i++) {
        int idx = tid + i * 256;
        int row = idx >> 3, seg = idx & 7;
        uint2 v = *(const uint2*)(src + (size_t)(rowBase + row) * NSTATE + k0 + seg * 4);
        *(uint2*)&S[row][seg * 4] = v;
    }
}

__global__ __launch_bounds__(256)
void gemm_mma(const float* __restrict__ bias, float* __restrict__ Cext,
              float scl, int aSel, int wIdx, int outSel)
{
    __shared__ __nv_bfloat16 Ash[128][LDW], Asl[128][LDW];
    __shared__ __nv_bfloat16 Bsh[128][LDW], Bsl[128][LDW];

    int tid = threadIdx.x;
    int wid = tid >> 5, l = tid & 31;
    int wm = wid >> 2, wn = wid & 3;          // 2 x 4 warp grid
    int mw0 = wm * 64, nw0 = wn * 32;
    int m0 = blockIdx.y * 128, n0 = blockIdx.x * 128;
    int gr = l >> 2, kc = (l & 3) * 2;

    const __nv_bfloat16* A_h = aSel ? g_WVh : g_xh;
    const __nv_bfloat16* A_l = aSel ? g_WVl : g_xl;
    const __nv_bfloat16* B_h = g_Wth + (size_t)wIdx * NSTATE * NSTATE;
    const __nv_bfloat16* B_l = g_Wtl + (size_t)wIdx * NSTATE * NSTATE;

    float c[4][4][4];
#pragma unroll
    for (int mt = 0; mt < 4; mt++)
#pragma unroll
        for (int nt = 0; nt < 4; nt++)
#pragma unroll
            for (int e = 0; e < 4; e++) c[mt][nt][e] = 0.f;

    for (int k0 = 0; k0 < NSTATE; k0 += 32) {
        __syncthreads();
        load_tile32(A_h, m0, k0, Ash, tid);
        load_tile32(A_l, m0, k0, Asl, tid);
        load_tile32(B_h, n0, k0, Bsh, tid);
        load_tile32(B_l, n0, k0, Bsl, tid);
        __syncthreads();

#pragma unroll
        for (int kk = 0; kk < 32; kk += 16) {
            uint32_t bh[4][2], bl[4][2];
#pragma unroll
            for (int nt = 0; nt < 4; nt++) {
                int nr = nw0 + nt * 8 + gr;
                bh[nt][0] = *(uint32_t*)&Bsh[nr][kk + kc];
                bh[nt][1] = *(uint32_t*)&Bsh[nr][kk + kc + 8];
                bl[nt][0] = *(uint32_t*)&Bsl[nr][kk + kc];
                bl[nt][1] = *(uint32_t*)&Bsl[nr][kk + kc + 8];
            }
#pragma unroll
            for (int mt = 0; mt < 4; mt++) {
                int r = mw0 + mt * 16;
                uint32_t ah[4], al[4];
                ah[0] = *(uint32_t*)&Ash[r + gr][kk + kc];
                ah[1] = *(uint32_t*)&Ash[r + gr + 8][kk + kc];
                ah[2] = *(uint32_t*)&Ash[r + gr][kk + kc + 8];
                ah[3] = *(uint32_t*)&Ash[r + gr + 8][kk + kc + 8];
                al[0] = *(uint32_t*)&Asl[r + gr][kk + kc];
                al[1] = *(uint32_t*)&Asl[r + gr + 8][kk + kc];
                al[2] = *(uint32_t*)&Asl[r + gr][kk + kc + 8];
                al[3] = *(uint32_t*)&Asl[r + gr + 8][kk + kc + 8];
#pragma unroll
                for (int nt = 0; nt < 4; nt++) {
                    mma16816(c[mt][nt], ah, bh[nt]);
                    mma16816(c[mt][nt], ah, bl[nt]);
                    mma16816(c[mt][nt], al, bh[nt]);
                }
            }
        }
    }

    // epilogue: v = (acc + bias[n]) * scl
#pragma unroll
    for (int mt = 0; mt < 4; mt++) {
#pragma unroll
        for (int nt = 0; nt < 4; nt++) {
            int n = n0 + nw0 + nt * 8 + kc;          // cols n, n+1
            float b0 = bias ? bias[n] : 0.f;
            float b1 = bias ? bias[n + 1] : 0.f;
#pragma unroll
            for (int half = 0; half < 2; half++) {
                int m = m0 + mw0 + mt * 16 + gr + half * 8;
                float v0 = (c[mt][nt][half * 2 + 0] + b0) * scl;
                float v1 = (c[mt][nt][half * 2 + 1] + b1) * scl;
                if (outSel == 3) {
                    float2* p = (float2*)(Cext + (size_t)m * NSTATE + n);
                    *p = make_float2(v0, v1);
                } else {
                    float* dst = (outSel == 0) ? g_Q : ((outSel == 1) ? g_K : g_V);
                    int b = m >> 11, s = m & (SDIM - 1);
                    int h = n >> 6, d = n & (HDIM - 1);
                    float2* p = (float2*)(dst + ((size_t)(b * NHEAD + h) * SDIM + s) * HDIM + d);
                    *p = make_float2(v0, v1);
                }
            }
        }
    }
}

// ---------------- fill upper-triangle of qk with -1e9 ----------------------
__global__ void fill_mask(float* __restrict__ qk)
{
    size_t i4 = (size_t)blockIdx.x * 256 + threadIdx.x;
    size_t base = i4 * 4;
    int k = (int)(base & (SDIM - 1));
    size_t row = base >> 11;
    int q = (int)(row & (SDIM - 1));
    if (k > q) {
        float4 v = make_float4(-1e9f, -1e9f, -1e9f, -1e9f);
        *(float4*)(qk + base) = v;
    } else if (k + 3 > q) {
#pragma unroll
        for (int e = 0; e < 4; e++)
            if (k + e > q) qk[base + e] = -1e9f;
    }
}

// ---------------- fp32 SIMT flash attention (writes qk logits) -------------
__global__ __launch_bounds__(256, 2)
void flash_kernel(float* __restrict__ qk_out)
{
    int qb = blockIdx.x, h = blockIdx.y, b = blockIdx.z;
    int bh = b * NHEAD + h;
    int q0 = qb * 32;

    __shared__ float Qs[32][68];
    __shared__ float Ks[64][68];
    __shared__ float Vs[64][68];

    int tid = threadIdx.x;
    int r = tid >> 3, l = tid & 7;
    int q = q0 + r;

    const float* Qg = g_Q + (size_t)bh * SDIM * HDIM;
    const float* Kg = g_K + (size_t)bh * SDIM * HDIM;
    const float* Vg = g_V + (size_t)bh * SDIM * HDIM;

#pragma unroll
    for (int i = 0; i < 2; i++) {
        int f = tid + i * 256;
        int row = f >> 4, c = (f & 15) << 2;
        *(float4*)&Qs[row][c] = *(const float4*)(Qg + (size_t)(q0 + row) * HDIM + c);
    }

    float oacc[64];
#pragma unroll
    for (int d = 0; d < 64; d++) oacc[d] = 0.f;
    float mrow = -INFINITY, lrow = 0.f;

    int nTiles = (q0 + 32 + 63) >> 6;
    for (int t = 0; t < nTiles; t++) {
        int k0 = t * 64;
        __syncthreads();
#pragma unroll
        for (int i = 0; i < 4; i++) {
            int f = tid + i * 256;
            int row = f >> 4, c = (f & 15) << 2;
            *(float4*)&Ks[row][c] = *(const float4*)(Kg + (size_t)(k0 + row) * HDIM + c);
            *(float4*)&Vs[row][c] = *(const float4*)(Vg + (size_t)(k0 + row) * HDIM + c);
        }
        __syncthreads();

        float sv[8];
#pragma unroll
        for (int j = 0; j < 8; j++) sv[j] = 0.f;
#pragma unroll
        for (int d = 0; d < 64; d += 4) {
            float4 qv = *(float4*)&Qs[r][d];
#pragma unroll
            for (int j = 0; j < 8; j++) {
                float4 kv = *(float4*)&Ks[j * 8 + l][d];
                sv[j] += qv.x * kv.x + qv.y * kv.y + qv.z * kv.z + qv.w * kv.w;
            }
        }

        float tmax = -INFINITY;
        float* qkrow = qk_out + ((size_t)bh * SDIM + q) * SDIM + k0;
#pragma unroll
        for (int j = 0; j < 8; j++) {
            int kg = k0 + j * 8 + l;
            if (kg > q) sv[j] = -1e9f;
            tmax = fmaxf(tmax, sv[j]);
            qkrow[j * 8 + l] = sv[j];
        }

        tmax = fmaxf(tmax, __shfl_xor_sync(0xffffffffu, tmax, 1));
        tmax = fmaxf(tmax, __shfl_xor_sync(0xffffffffu, tmax, 2));
        tmax = fmaxf(tmax, __shfl_xor_sync(0xffffffffu, tmax, 4));
        float mnew = fmaxf(mrow, tmax);
        float fac = __expf(mrow - mnew);

        float p[8], psum = 0.f;
#pragma unroll
        for (int j = 0; j < 8; j++) { p[j] = __expf(sv[j] - mnew); psum += p[j]; }
        psum += __shfl_xor_sync(0xffffffffu, psum, 1);
        psum += __shfl_xor_sync(0xffffffffu, psum, 2);
        psum += __shfl_xor_sync(0xffffffffu, psum, 4);
        lrow = lrow * fac + psum;
        mrow = mnew;

#pragma unroll
        for (int d = 0; d < 64; d++) oacc[d] *= fac;
#pragma unroll
        for (int j = 0; j < 8; j++) {
            float pj = p[j];
#pragma unroll
            for (int d = 0; d < 64; d += 4) {
                float4 vv = *(float4*)&Vs[j * 8 + l][d];
                oacc[d]     += pj * vv.x;
                oacc[d + 1] += pj * vv.y;
                oacc[d + 2] += pj * vv.z;
                oacc[d + 3] += pj * vv.w;
            }
        }
    }

#pragma unroll
    for (int d = 0; d < 32; d++) {
        float a = oacc[d], bb = oacc[d + 32];
        float send = (l & 4) ? a : bb;
        float recv = __shfl_xor_sync(0xffffffffu, send, 4);
        oacc[d] = ((l & 4) ? bb : a) + recv;
    }
#pragma unroll
    for (int d = 0; d < 16; d++) {
        float a = oacc[d], bb = oacc[d + 16];
        float send = (l & 2) ? a : bb;
        float recv = __shfl_xor_sync(0xffffffffu, send, 2);
        oacc[d] = ((l & 2) ? bb : a) + recv;
    }
#pragma unroll
    for (int d = 0; d < 8; d++) {
        float a = oacc[d], bb = oacc[d + 8];
        float send = (l & 1) ? a : bb;
        float recv = __shfl_xor_sync(0xffffffffu, send, 1);
        oacc[d] = ((l & 1) ? bb : a) + recv;
    }

    float inv = 1.f / lrow;
    float* wvrow = g_WV + ((size_t)(b * SDIM + q) * NHEAD + h) * HDIM + l * 8;
    float4 o0 = make_float4(oacc[0] * inv, oacc[1] * inv, oacc[2] * inv, oacc[3] * inv);
    float4 o1 = make_float4(oacc[4] * inv, oacc[5] * inv, oacc[6] * inv, oacc[7] * inv);
    *(float4*)(wvrow)     = o0;
    *(float4*)(wvrow + 4) = o1;
}

// ---------------------------------------------------------------------------
extern "C" void kernel_launch(void* const* d_in, const int* in_sizes, int n_in,
                              void* d_out, int out_size)
{
    const float* x  = (const float*)d_in[0];
    const float* Wq = (const float*)d_in[2];
    const float* bq = (const float*)d_in[3];
    const float* Wk = (const float*)d_in[4];
    const float* Wv = (const float*)d_in[5];
    const float* bv = (const float*)d_in[6];
    const float* Wo = (const float*)d_in[7];
    const float* bo = (const float*)d_in[8];

    float* out = (float*)d_out;                       // [b,s,1024]
    float* qk  = out + (size_t)BDIM * SDIM * NSTATE;  // [b,h,s,s]

    convert_x_kernel<<<MROWS * NSTATE / 4 / 256, 256>>>(x);
    transpose_convert<<<dim3(32, 32, 4), dim3(32, 8)>>>(Wq, Wk, Wv, Wo);

    dim3 g(NSTATE / 128, MROWS / 128);   // (8, 32)
    gemm_mma<<<g, 256>>>(bq, nullptr, SCALE_QK, 0, 0, 0);
    gemm_mma<<<g, 256>>>(nullptr, nullptr, SCALE_QK, 0, 1, 1);
    gemm_mma<<<g, 256>>>(bv, nullptr, 1.0f, 0, 2, 2);

    size_t qk_f4 = (size_t)BDIM * NHEAD * SDIM * SDIM / 4;
    fill_mask<<<(unsigned)(qk_f4 / 256), 256>>>(qk);

    flash_kernel<<<dim3(SDIM / 32, NHEAD, BDIM), 256>>>(qk);

    convert_wv_kernel<<<MROWS * NSTATE / 4 / 256, 256>>>();
    gemm_mma<<<g, 256>>>(bo, out, 1.0f, 1, 3, 3);
}